// round 16
// baseline (speedup 1.0000x reference)
#include <cuda_runtime.h>
#include <cstdint>
#include <cstddef>

// MNIST_RNN: 2-layer LSTM (H=10), T=28, D=28, B=32768, + 10-way linear head.
// R15: 4-way gate split across a lane QUAD, 2 elements per quad.
//  - lane role r (tid&3) owns gate type r (gates 10r..10r+9) for elems A,B
//  - weights laid out so each LDS.128 delivers DIFFERENT data per role:
//    per-warp LDS.128 drops 300 -> 145 at 2048 warps (R14 measured the L1
//    charge is per-instruction: 2 wavefronts per LDS.128 regardless of
//    uniformity). L1 and fma both land at the ~112k-cycle chip floor.
//  - cell update: each lane owns 5 stable (elem, hidden-parity) cell slots;
//    gate scalars exchanged via 3 shfl rotation rounds + uniform SEL gather.
// Volatile LDS (anti-LICM, R3); exp/rcp activations (tanh.approx emulated).

#define TT 28
#define DD 28
#define HH 10

typedef unsigned long long u64;
typedef unsigned int u32;

__device__ __forceinline__ u32 smem_u32(const void *p) {
    u32 a;
    asm("{ .reg .u64 t; cvta.to.shared.u64 t, %1; cvt.u32.u64 %0, t; }"
        : "=r"(a) : "l"(p));
    return a;
}
__device__ __forceinline__ u64 pack2(float lo, float hi) {
    u64 r;
    asm("mov.b64 %0, {%1, %2};" : "=l"(r) : "f"(lo), "f"(hi));
    return r;
}
__device__ __forceinline__ void unpack2(u64 v, float &lo, float &hi) {
    asm("mov.b64 {%0, %1}, %2;" : "=f"(lo), "=f"(hi) : "l"(v));
}
__device__ __forceinline__ u64 ffma2(u64 a, u64 b, u64 c) {
    u64 d;
    asm("fma.rn.f32x2 %0, %1, %2, %3;" : "=l"(d) : "l"(a), "l"(b), "l"(c));
    return d;
}
// Non-hoistable shared loads (volatile = opaque to LICM/CSE; see R3).
__device__ __forceinline__ void lds_v2u64(u64 &w0, u64 &w1, u32 addr) {
    asm volatile("ld.shared.v2.u64 {%0, %1}, [%2];"
                 : "=l"(w0), "=l"(w1) : "r"(addr));
}
__device__ __forceinline__ float shfl_f(float v, int src) {
    return __shfl_sync(0xffffffffu, v, src);
}

// exp/rcp-based activations (MUFU.EX2 + MUFU.RCP): ~1e-6 abs error.
__device__ __forceinline__ float sigf(float x) {
    return __fdividef(1.0f, 1.0f + __expf(-x));
}
__device__ __forceinline__ float tanhf_(float x) {
    return 1.0f - 2.0f * __fdividef(1.0f, 1.0f + __expf(x + x));
}

// 4-way select by lane-uniform runtime index kk (0..3).
#define SEL4(o_, a1_, a2_, a3_, kk) \
    ((kk) == 0 ? (o_) : (kk) == 1 ? (a1_) : (kk) == 2 ? (a2_) : (a3_))

// smem blob layout (u64 units). Row-pair-major, role-minor regions:
// region element [P][r][10 u64]: slots 0-4 = row 2P gates (10r+2s,10r+2s+1),
// slots 5-9 = row 2P+1. Pair stride = 320 B, role stride = 80 B.
//  w0x: 14 pairs @0 (560)   w0h: 5 pairs @560 (200)
//  w1x: @760 (200)          w1h: @960 (200)
//  b0: @1160 (4 roles x 6 u64, padded)  b1: @1184  -> total 1208 u64
#define U_W0X 0
#define U_W0H 560
#define U_W1X 760
#define U_W1H 960
#define U_B0  1160
#define U_B1  1184
#define U_TOT 1208

// One row-pair accumulation: 5 LDS.128 (role-distinct data) + 20 FFMA2.
#define ACCP(LB, P, xa0, xb0, xa1, xb1)                                 \
    {                                                                   \
        u64 w_[10];                                                     \
        _Pragma("unroll")                                               \
        for (int k = 0; k < 5; k++)                                     \
            lds_v2u64(w_[2 * k], w_[2 * k + 1], (LB) + (P) * 320 + k * 16); \
        u64 va0 = pack2((xa0), (xa0)), vb0 = pack2((xb0), (xb0));       \
        u64 va1 = pack2((xa1), (xa1)), vb1 = pack2((xb1), (xb1));       \
        _Pragma("unroll")                                               \
        for (int j = 0; j < 5; j++) {                                   \
            aA[j] = ffma2(va0, w_[j], aA[j]);                           \
            aB[j] = ffma2(vb0, w_[j], aB[j]);                           \
        }                                                               \
        _Pragma("unroll")                                               \
        for (int j = 0; j < 5; j++) {                                   \
            aA[j] = ffma2(va1, w_[5 + j], aA[j]);                       \
            aB[j] = ffma2(vb1, w_[5 + j], aB[j]);                       \
        }                                                               \
    }

// Init accumulators from padded bias region (3 LDS.128; 6th u64 unused).
#define INIT_BIAS(BB)                                                   \
    {                                                                   \
        u64 t0, t1, t2, t3, t4, t5;                                     \
        lds_v2u64(t0, t1, (BB));                                        \
        lds_v2u64(t2, t3, (BB) + 16);                                   \
        lds_v2u64(t4, t5, (BB) + 32);                                   \
        aA[0] = t0; aA[1] = t1; aA[2] = t2; aA[3] = t3; aA[4] = t4;     \
        aB[0] = t0; aB[1] = t1; aB[2] = t2; aB[3] = t3; aB[4] = t4;     \
        (void)t5;                                                       \
    }

// Quad exchange + pointwise update. Lane owns gate type `role` for elems
// A,B; updates its 5 stable slots (elem myB, hidden 2j+myp) in cv[5];
// then redistributes h so every lane gets full hAo[10], hBo[10].
#define EXCH_UPDATE4(hAo, hBo, cv)                                      \
    {                                                                   \
        float own_[5], r1_[5], r2_[5], r3_[5];                          \
        _Pragma("unroll")                                               \
        for (int j = 0; j < 5; j++) {                                   \
            float lo_, hi_;                                             \
            unpack2(myB ? aB[j] : aA[j], lo_, hi_);                     \
            own_[j] = myp ? hi_ : lo_;                                  \
        }                                                               \
        _Pragma("unroll")                                               \
        for (int j = 0; j < 5; j++) {                                   \
            float lo_, hi_;                                             \
            unpack2((rr1 >= 2) ? aB[j] : aA[j], lo_, hi_);              \
            r1_[j] = shfl_f((rr1 & 1) ? hi_ : lo_, s1);                 \
        }                                                               \
        _Pragma("unroll")                                               \
        for (int j = 0; j < 5; j++) {                                   \
            float lo_, hi_;                                             \
            unpack2((rr2 >= 2) ? aB[j] : aA[j], lo_, hi_);              \
            r2_[j] = shfl_f((rr2 & 1) ? hi_ : lo_, s2);                 \
        }                                                               \
        _Pragma("unroll")                                               \
        for (int j = 0; j < 5; j++) {                                   \
            float lo_, hi_;                                             \
            unpack2((rr3 >= 2) ? aB[j] : aA[j], lo_, hi_);              \
            r3_[j] = shfl_f((rr3 & 1) ? hi_ : lo_, s3);                 \
        }                                                               \
        float hm_[5];                                                   \
        _Pragma("unroll")                                               \
        for (int j = 0; j < 5; j++) {                                   \
            float gi_ = SEL4(own_[j], r1_[j], r2_[j], r3_[j], k0);      \
            float gf_ = SEL4(own_[j], r1_[j], r2_[j], r3_[j], k1);      \
            float gg_ = SEL4(own_[j], r1_[j], r2_[j], r3_[j], k2);      \
            float go_ = SEL4(own_[j], r1_[j], r2_[j], r3_[j], k3);      \
            float cn = sigf(gf_) * cv[j] + sigf(gi_) * tanhf_(gg_);     \
            cv[j] = cn;                                                 \
            hm_[j] = sigf(go_) * tanhf_(cn);                            \
        }                                                               \
        float h1r[5], h2r[5], h3r[5];                                   \
        _Pragma("unroll")                                               \
        for (int j = 0; j < 5; j++) {                                   \
            h1r[j] = shfl_f(hm_[j], s1);                                \
            h2r[j] = shfl_f(hm_[j], s2);                                \
            h3r[j] = shfl_f(hm_[j], s3);                                \
        }                                                               \
        _Pragma("unroll")                                               \
        for (int j = 0; j < 5; j++) {                                   \
            hAo[2 * j]     = SEL4(hm_[j], h1r[j], h2r[j], h3r[j], k0);  \
            hAo[2 * j + 1] = SEL4(hm_[j], h1r[j], h2r[j], h3r[j], k1);  \
            hBo[2 * j]     = SEL4(hm_[j], h1r[j], h2r[j], h3r[j], k2);  \
            hBo[2 * j + 1] = SEL4(hm_[j], h1r[j], h2r[j], h3r[j], k3);  \
        }                                                               \
    }

__global__ __launch_bounds__(32)
void mnist_rnn_kernel(const float *__restrict__ x,
                      const float *__restrict__ wih0, const float *__restrict__ whh0,
                      const float *__restrict__ bih0, const float *__restrict__ bhh0,
                      const float *__restrict__ wih1, const float *__restrict__ whh1,
                      const float *__restrict__ bih1, const float *__restrict__ bhh1,
                      const float *__restrict__ wcls, const float *__restrict__ bcls,
                      float *__restrict__ out, int B) {
    __shared__ u64 blob[U_TOT];
    __shared__ float swc[100], sbc[10];

    const int tid = threadIdx.x;
    {
        float *f = (float *)blob;
        // weight regions: [P][r][10 u64]; slot s<5 -> row 2P, s>=5 -> row 2P+1
        for (int i = tid; i < 1120; i += 32) {              // w0x (rows=28)
            int P = i / 80, rem = i % 80, r = rem / 20, q = rem % 20;
            int s = q / 2, hh = q % 2;
            int row = 2 * P + (s >= 5), gate = 10 * r + 2 * (s % 5) + hh;
            f[i] = wih0[gate * DD + row];
        }
        for (int i = tid; i < 400; i += 32) {               // w0h/w1x/w1h (rows=10)
            int P = i / 80, rem = i % 80, r = rem / 20, q = rem % 20;
            int s = q / 2, hh = q % 2;
            int row = 2 * P + (s >= 5), gate = 10 * r + 2 * (s % 5) + hh;
            f[1120 + i] = whh0[gate * HH + row];
            f[1520 + i] = wih1[gate * HH + row];
            f[1920 + i] = whh1[gate * HH + row];
        }
        for (int i = tid; i < 48; i += 32) {                // b0/b1 padded
            int r = i / 12, q = i % 12, s = q / 2, hh = q % 2;
            float v0 = 0.f, v1 = 0.f;
            if (s < 5) {
                int gate = 10 * r + 2 * s + hh;
                v0 = bih0[gate] + bhh0[gate];
                v1 = bih1[gate] + bhh1[gate];
            }
            f[2320 + i] = v0;
            f[2368 + i] = v1;
        }
        for (int i = tid; i < 100; i += 32) swc[i] = wcls[i];
        for (int i = tid; i < 10; i += 32) sbc[i] = bcls[i];
    }
    __syncthreads();

    const u32 sbase = smem_u32(blob);
    const int role = tid & 3;
    const int qb = tid & ~3;
    const bool myB = role >= 2;          // my element: 0 -> A, 1 -> B
    const int myp = role & 1;            // my hidden parity
    // rotation sources and the receiver-role I serve in each round
    const int s1 = qb | ((role + 1) & 3);
    const int s2 = qb | ((role + 2) & 3);
    const int s3 = qb | ((role + 3) & 3);
    const int rr1 = (role + 3) & 3;      // (role-1)&3
    const int rr2 = (role + 2) & 3;
    const int rr3 = (role + 1) & 3;
    // gather index for absolute gate-type / source-role t: (t - role) & 3
    const int k0 = (0 - role) & 3, k1 = (1 - role) & 3;
    const int k2 = (2 - role) & 3, k3 = (3 - role) & 3;

    const u32 w0x_L = sbase + U_W0X * 8 + role * 80;
    const u32 w0h_L = sbase + U_W0H * 8 + role * 80;
    const u32 w1x_L = sbase + U_W1X * 8 + role * 80;
    const u32 w1h_L = sbase + U_W1H * 8 + role * 80;
    const u32 b0_L  = sbase + U_B0 * 8 + role * 48;
    const u32 b1_L  = sbase + U_B1 * 8 + role * 48;

    const int Bh = B >> 1;
    const int pairIdx = blockIdx.x * 8 + (tid >> 2);   // 8 quads per CTA
    if (pairIdx >= Bh) return;
    const int bA = pairIdx, bB = pairIdx + Bh;

    const float *xbA = x + (size_t)bA * (TT * DD);
    const float *xbB = x + (size_t)bB * (TT * DD);

    float h0A[HH], h0B[HH], h1A[HH], h1B[HH];   // full hidden vectors
    float c0m[5], c1m[5];                        // my 5 cell slots per layer
#pragma unroll
    for (int j = 0; j < HH; j++) {
        h0A[j] = 0.f; h0B[j] = 0.f; h1A[j] = 0.f; h1B[j] = 0.f;
    }
#pragma unroll
    for (int j = 0; j < 5; j++) { c0m[j] = 0.f; c1m[j] = 0.f; }

#pragma unroll 1
    for (int t = 0; t < TT; t++) {
        const float4 *xrA = reinterpret_cast<const float4 *>(xbA + t * DD);
        const float4 *xrB = reinterpret_cast<const float4 *>(xbB + t * DD);

        u64 aA[5], aB[5];

        // ---- layer 0: x projection over 14 row-pairs, pipelined x ----
        INIT_BIAS(b0_L)
        float4 xa = xrA[0], xb = xrB[0];
        float4 na = xrA[1], nb = xrB[1];
        ACCP(w0x_L, 0, xa.x, xb.x, xa.y, xb.y)
        ACCP(w0x_L, 1, xa.z, xb.z, xa.w, xb.w)
        xa = na; xb = nb; na = xrA[2]; nb = xrB[2];
        ACCP(w0x_L, 2, xa.x, xb.x, xa.y, xb.y)
        ACCP(w0x_L, 3, xa.z, xb.z, xa.w, xb.w)
        xa = na; xb = nb; na = xrA[3]; nb = xrB[3];
        ACCP(w0x_L, 4, xa.x, xb.x, xa.y, xb.y)
        ACCP(w0x_L, 5, xa.z, xb.z, xa.w, xb.w)
        xa = na; xb = nb; na = xrA[4]; nb = xrB[4];
        ACCP(w0x_L, 6, xa.x, xb.x, xa.y, xb.y)
        ACCP(w0x_L, 7, xa.z, xb.z, xa.w, xb.w)
        xa = na; xb = nb; na = xrA[5]; nb = xrB[5];
        ACCP(w0x_L, 8, xa.x, xb.x, xa.y, xb.y)
        ACCP(w0x_L, 9, xa.z, xb.z, xa.w, xb.w)
        xa = na; xb = nb; na = xrA[6]; nb = xrB[6];
        ACCP(w0x_L, 10, xa.x, xb.x, xa.y, xb.y)
        ACCP(w0x_L, 11, xa.z, xb.z, xa.w, xb.w)
        xa = na; xb = nb;
        ACCP(w0x_L, 12, xa.x, xb.x, xa.y, xb.y)
        ACCP(w0x_L, 13, xa.z, xb.z, xa.w, xb.w)

        // recurrent part of layer 0
        ACCP(w0h_L, 0, h0A[0], h0B[0], h0A[1], h0B[1])
        ACCP(w0h_L, 1, h0A[2], h0B[2], h0A[3], h0B[3])
        ACCP(w0h_L, 2, h0A[4], h0B[4], h0A[5], h0B[5])
        ACCP(w0h_L, 3, h0A[6], h0B[6], h0A[7], h0B[7])
        ACCP(w0h_L, 4, h0A[8], h0B[8], h0A[9], h0B[9])
        EXCH_UPDATE4(h0A, h0B, c0m)

        // ---- layer 1 ----
        INIT_BIAS(b1_L)
        ACCP(w1x_L, 0, h0A[0], h0B[0], h0A[1], h0B[1])
        ACCP(w1x_L, 1, h0A[2], h0B[2], h0A[3], h0B[3])
        ACCP(w1x_L, 2, h0A[4], h0B[4], h0A[5], h0B[5])
        ACCP(w1x_L, 3, h0A[6], h0B[6], h0A[7], h0B[7])
        ACCP(w1x_L, 4, h0A[8], h0B[8], h0A[9], h0B[9])
        ACCP(w1h_L, 0, h1A[0], h1B[0], h1A[1], h1B[1])
        ACCP(w1h_L, 1, h1A[2], h1B[2], h1A[3], h1B[3])
        ACCP(w1h_L, 2, h1A[4], h1B[4], h1A[5], h1B[5])
        ACCP(w1h_L, 3, h1A[6], h1B[6], h1A[7], h1B[7])
        ACCP(w1h_L, 4, h1A[8], h1B[8], h1A[9], h1B[9])
        EXCH_UPDATE4(h1A, h1B, c1m)
    }

    // classifier head: role0 writes elem A, role2 writes elem B
    if (role == 0 || role == 2) {
        const int bm = (role == 0) ? bA : bB;
        const float *hv = (role == 0) ? h1A : h1B;
#pragma unroll
        for (int k = 0; k < 10; k++) {
            float s = sbc[k];
#pragma unroll
            for (int j = 0; j < HH; j++) s += hv[j] * swc[k * HH + j];
            out[(size_t)bm * 10 + k] = s;
        }
    }
}

extern "C" void kernel_launch(void *const *d_in, const int *in_sizes, int n_in,
                              void *d_out, int out_size) {
    const float *x    = (const float *)d_in[0];
    const float *wih0 = (const float *)d_in[1];
    const float *whh0 = (const float *)d_in[2];
    const float *bih0 = (const float *)d_in[3];
    const float *bhh0 = (const float *)d_in[4];
    const float *wih1 = (const float *)d_in[5];
    const float *whh1 = (const float *)d_in[6];
    const float *bih1 = (const float *)d_in[7];
    const float *bhh1 = (const float *)d_in[8];
    const float *wcls = (const float *)d_in[9];
    const float *bcls = (const float *)d_in[10];
    float *out = (float *)d_out;

    const int B = in_sizes[0] / (TT * DD);
    const int Bh = B >> 1;
    const int grid = (Bh + 7) / 8;   // 8 quads (16 elems) per 32-thread CTA
    mnist_rnn_kernel<<<grid, 32>>>(x, wih0, whh0, bih0, bhh0,
                                   wih1, whh1, bih1, bhh1,
                                   wcls, bcls, out, B);
}

// round 17
// speedup vs baseline: 1.7724x; 1.7724x over previous
#include <cuda_runtime.h>
#include <cstdint>
#include <cstddef>

// MNIST_RNN: 2-layer LSTM (H=10), T=28, D=28, B=32768, + 10-way linear head.
// R16: 4-way split by (gate-half, parity) across a lane QUAD, 2 elems/quad.
//  - lane role r: hr=r>>1 selects (i,f) vs (g,o); pr=r&1 selects hidden
//    parity. Lane owns pairs (lo,hi)[2j+pr] for BOTH elems (ratio 4: each
//    LDS.128 feeds 4 FFMA2) -> 2048 warps AND per-warp LDS 145/step.
//  - cell update: lane updates cells (elem hr, h=2j+pr). It owns half the
//    gates; other half arrives via ONE shfl.xor(2) round (10 shfl/layer).
//    h redistributed via padded smem buffer (fixed layout, no selects) --
//    this removes R15's SEL4 cascades (alu was 19.3%).
// Volatile LDS (anti-LICM, R3); exp/rcp activations (tanh.approx emulated).

#define TT 28
#define DD 28
#define HH 10

typedef unsigned long long u64;
typedef unsigned int u32;

__device__ __forceinline__ u32 smem_u32(const void *p) {
    u32 a;
    asm("{ .reg .u64 t; cvta.to.shared.u64 t, %1; cvt.u32.u64 %0, t; }"
        : "=r"(a) : "l"(p));
    return a;
}
__device__ __forceinline__ u64 pack2(float lo, float hi) {
    u64 r;
    asm("mov.b64 %0, {%1, %2};" : "=l"(r) : "f"(lo), "f"(hi));
    return r;
}
__device__ __forceinline__ void unpack2(u64 v, float &lo, float &hi) {
    asm("mov.b64 {%0, %1}, %2;" : "=f"(lo), "=f"(hi) : "l"(v));
}
__device__ __forceinline__ u64 ffma2(u64 a, u64 b, u64 c) {
    u64 d;
    asm("fma.rn.f32x2 %0, %1, %2, %3;" : "=l"(d) : "l"(a), "l"(b), "l"(c));
    return d;
}
// Non-hoistable shared ops (volatile = opaque to LICM/CSE; see R3).
__device__ __forceinline__ void lds_v2u64(u64 &w0, u64 &w1, u32 addr) {
    asm volatile("ld.shared.v2.u64 {%0, %1}, [%2];"
                 : "=l"(w0), "=l"(w1) : "r"(addr));
}
__device__ __forceinline__ void sts128(u32 addr, float a, float b, float c, float d) {
    asm volatile("st.shared.v4.f32 [%0], {%1, %2, %3, %4};"
                 :: "r"(addr), "f"(a), "f"(b), "f"(c), "f"(d) : "memory");
}
__device__ __forceinline__ void sts32(u32 addr, float a) {
    asm volatile("st.shared.f32 [%0], %1;" :: "r"(addr), "f"(a) : "memory");
}
__device__ __forceinline__ void lds128(u32 addr, float &a, float &b, float &c, float &d) {
    asm volatile("ld.shared.v4.f32 {%0, %1, %2, %3}, [%4];"
                 : "=f"(a), "=f"(b), "=f"(c), "=f"(d) : "r"(addr));
}
__device__ __forceinline__ void lds32(u32 addr, float &a) {
    asm volatile("ld.shared.f32 %0, [%1];" : "=f"(a) : "r"(addr));
}
__device__ __forceinline__ u64 shflx2_u64(u64 v) {
    u32 lo, hi;
    asm("mov.b64 {%0, %1}, %2;" : "=r"(lo), "=r"(hi) : "l"(v));
    lo = __shfl_xor_sync(0xffffffffu, lo, 2);
    hi = __shfl_xor_sync(0xffffffffu, hi, 2);
    u64 r;
    asm("mov.b64 %0, {%1, %2};" : "=l"(r) : "r"(lo), "r"(hi));
    return r;
}

// exp/rcp-based activations (MUFU.EX2 + MUFU.RCP): ~1e-6 abs error.
__device__ __forceinline__ float sigf(float x) {
    return __fdividef(1.0f, 1.0f + __expf(-x));
}
__device__ __forceinline__ float tanhf_(float x) {
    return 1.0f - 2.0f * __fdividef(1.0f, 1.0f + __expf(x + x));
}

// smem blob (u64 units): regions [P][role][10 u64]; role stride 80 B,
// pair stride 320 B. slots 0-4 = row 2P, 5-9 = row 2P+1.
//  w0x: 14 pairs @0   w0h: 5 pairs @560   w1x @760   w1h @960
//  b0: @1160 (4 roles x 6 u64 padded)  b1: @1184  -> 1208 u64
#define U_W0X 0
#define U_W0H 560
#define U_W1X 760
#define U_W1H 960
#define U_B0  1160
#define U_B1  1184
#define U_TOT 1208

// One row-pair: 5 LDS.128 (role-distinct weights) + 20 FFMA2 (2 elems).
#define ACCP(LB, P, xa0, xb0, xa1, xb1)                                 \
    {                                                                   \
        u64 w_[10];                                                     \
        _Pragma("unroll")                                               \
        for (int k = 0; k < 5; k++)                                     \
            lds_v2u64(w_[2 * k], w_[2 * k + 1], (LB) + (P) * 320 + k * 16); \
        u64 va0 = pack2((xa0), (xa0)), vb0 = pack2((xb0), (xb0));       \
        u64 va1 = pack2((xa1), (xa1)), vb1 = pack2((xb1), (xb1));       \
        _Pragma("unroll")                                               \
        for (int j = 0; j < 5; j++) {                                   \
            aA[j] = ffma2(va0, w_[j], aA[j]);                           \
            aB[j] = ffma2(vb0, w_[j], aB[j]);                           \
        }                                                               \
        _Pragma("unroll")                                               \
        for (int j = 0; j < 5; j++) {                                   \
            aA[j] = ffma2(va1, w_[5 + j], aA[j]);                       \
            aB[j] = ffma2(vb1, w_[5 + j], aB[j]);                       \
        }                                                               \
    }

// Init accs from padded bias region (3 LDS.128; 6th u64 unused).
#define INIT_BIAS(BB)                                                   \
    {                                                                   \
        u64 t0, t1, t2, t3, t4, t5;                                     \
        lds_v2u64(t0, t1, (BB));                                        \
        lds_v2u64(t2, t3, (BB) + 16);                                   \
        lds_v2u64(t4, t5, (BB) + 32);                                   \
        aA[0] = t0; aA[1] = t1; aA[2] = t2; aA[3] = t3; aA[4] = t4;     \
        aB[0] = t0; aB[1] = t1; aB[2] = t2; aB[3] = t3; aB[4] = t4;     \
        (void)t5;                                                       \
    }

// Half-exchange + update + smem h all-gather.
// hr=0 lane: owns (i,f) both elems; cell-elem A. Sends aB, receives (g,o)A.
// hr=1 lane: owns (g,o) both elems; cell-elem B. Sends aA, receives (i,f)B.
#define EXCH_UPDATE(hAo, hBo, cv)                                       \
    {                                                                   \
        u64 rcvv[5];                                                    \
        _Pragma("unroll")                                               \
        for (int j = 0; j < 5; j++) {                                   \
            u64 snd = hr ? aA[j] : aB[j];                               \
            rcvv[j] = shflx2_u64(snd);                                  \
        }                                                               \
        float hm_[5];                                                   \
        _Pragma("unroll")                                               \
        for (int j = 0; j < 5; j++) {                                   \
            u64 pif = hr ? rcvv[j] : aA[j];                             \
            u64 pgo = hr ? aB[j] : rcvv[j];                             \
            float i_s, f_s, g_s, o_s;                                   \
            unpack2(pif, i_s, f_s);                                     \
            unpack2(pgo, g_s, o_s);                                     \
            float cn = sigf(f_s) * cv[j] + sigf(i_s) * tanhf_(g_s);     \
            cv[j] = cn;                                                 \
            hm_[j] = sigf(o_s) * tanhf_(cn);                            \
        }                                                               \
        sts128(hxw, hm_[0], hm_[1], hm_[2], hm_[3]);                    \
        sts32(hxw + 16, hm_[4]);                                        \
        __syncwarp();                                                   \
        {                                                               \
            float f0, f1, f2, f3, f4;                                   \
            lds128(hxr, f0, f1, f2, f3); lds32(hxr + 16, f4);           \
            hAo[0] = f0; hAo[2] = f1; hAo[4] = f2; hAo[6] = f3; hAo[8] = f4; \
            lds128(hxr + 32, f0, f1, f2, f3); lds32(hxr + 48, f4);      \
            hAo[1] = f0; hAo[3] = f1; hAo[5] = f2; hAo[7] = f3; hAo[9] = f4; \
            lds128(hxr + 64, f0, f1, f2, f3); lds32(hxr + 80, f4);      \
            hBo[0] = f0; hBo[2] = f1; hBo[4] = f2; hBo[6] = f3; hBo[8] = f4; \
            lds128(hxr + 96, f0, f1, f2, f3); lds32(hxr + 112, f4);     \
            hBo[1] = f0; hBo[3] = f1; hBo[5] = f2; hBo[7] = f3; hBo[9] = f4; \
        }                                                               \
        __syncwarp();                                                   \
    }

__global__ __launch_bounds__(32)
void mnist_rnn_kernel(const float *__restrict__ x,
                      const float *__restrict__ wih0, const float *__restrict__ whh0,
                      const float *__restrict__ bih0, const float *__restrict__ bhh0,
                      const float *__restrict__ wih1, const float *__restrict__ whh1,
                      const float *__restrict__ bih1, const float *__restrict__ bhh1,
                      const float *__restrict__ wcls, const float *__restrict__ bcls,
                      float *__restrict__ out, int B) {
    __shared__ u64 blob[U_TOT];
    __shared__ float hx[8 * 36];   // per-quad 144 B (36 floats): 4 groups x 32 B

    const int tid = threadIdx.x;
    {
        float *f = (float *)blob;
        // weight pack: pair (lo,hi) for role (pr,hr): lo = (hr?g:i)[2j+pr],
        // hi = (hr?o:f)[2j+pr]; gate ids: i=h, f=10+h, g=20+h, o=30+h.
        for (int i = tid; i < 1120; i += 32) {              // w0x (28 rows)
            int u = i >> 1, hw = i & 1;
            int P = u / 40, rem = u % 40, r = rem / 10, s = rem % 10;
            int pr = r & 1, hr = r >> 1;
            int row = 2 * P + (s >= 5), j = s % 5;
            int gate = (hw ? (hr ? 30 : 10) : (hr ? 20 : 0)) + 2 * j + pr;
            f[i] = wih0[gate * DD + row];
        }
        for (int i = tid; i < 400; i += 32) {               // w0h/w1x/w1h (10 rows)
            int u = i >> 1, hw = i & 1;
            int P = u / 40, rem = u % 40, r = rem / 10, s = rem % 10;
            int pr = r & 1, hr = r >> 1;
            int row = 2 * P + (s >= 5), j = s % 5;
            int gate = (hw ? (hr ? 30 : 10) : (hr ? 20 : 0)) + 2 * j + pr;
            f[1120 + i] = whh0[gate * HH + row];
            f[1520 + i] = wih1[gate * HH + row];
            f[1920 + i] = whh1[gate * HH + row];
        }
        for (int i = tid; i < 48; i += 32) {                // b0/b1 padded
            int r = i / 12, q = i % 12, u = q >> 1, hw = q & 1;
            int pr = r & 1, hr = r >> 1;
            float v0 = 0.f, v1 = 0.f;
            if (u < 5) {
                int gate = (hw ? (hr ? 30 : 10) : (hr ? 20 : 0)) + 2 * u + pr;
                v0 = bih0[gate] + bhh0[gate];
                v1 = bih1[gate] + bhh1[gate];
            }
            f[2320 + i] = v0;
            f[2368 + i] = v1;
        }
    }
    __syncthreads();

    const u32 sbase = smem_u32(blob);
    const u32 hxbase = smem_u32(hx);
    const int role = tid & 3;
    const int pr = role & 1;   (void)pr;
    const int hr = role >> 1;
    const int quad = tid >> 2;

    const u32 w0x_L = sbase + U_W0X * 8 + role * 80;
    const u32 w0h_L = sbase + U_W0H * 8 + role * 80;
    const u32 w1x_L = sbase + U_W1X * 8 + role * 80;
    const u32 w1h_L = sbase + U_W1H * 8 + role * 80;
    const u32 b0_L  = sbase + U_B0 * 8 + role * 48;
    const u32 b1_L  = sbase + U_B1 * 8 + role * 48;
    const u32 hxw = hxbase + quad * 144 + role * 32;   // my write slot
    const u32 hxr = hxbase + quad * 144;               // group base for reads

    const int Bh = B >> 1;
    const int pairIdx = blockIdx.x * 8 + quad;   // 8 quads per CTA
    if (pairIdx >= Bh) return;
    const int bA = pairIdx, bB = pairIdx + Bh;

    const float *xbA = x + (size_t)bA * (TT * DD);
    const float *xbB = x + (size_t)bB * (TT * DD);

    float h0A[HH], h0B[HH], h1A[HH], h1B[HH];   // full hidden vectors
    float c0m[5], c1m[5];                        // my 5 cells per layer
#pragma unroll
    for (int j = 0; j < HH; j++) {
        h0A[j] = 0.f; h0B[j] = 0.f; h1A[j] = 0.f; h1B[j] = 0.f;
    }
#pragma unroll
    for (int j = 0; j < 5; j++) { c0m[j] = 0.f; c1m[j] = 0.f; }

#pragma unroll 1
    for (int t = 0; t < TT; t++) {
        const float4 *xrA = reinterpret_cast<const float4 *>(xbA + t * DD);
        const float4 *xrB = reinterpret_cast<const float4 *>(xbB + t * DD);

        u64 aA[5], aB[5];

        // ---- layer 0: x projection over 14 row-pairs, pipelined x ----
        INIT_BIAS(b0_L)
        float4 xa = xrA[0], xb = xrB[0];
        float4 na = xrA[1], nb = xrB[1];
        ACCP(w0x_L, 0, xa.x, xb.x, xa.y, xb.y)
        ACCP(w0x_L, 1, xa.z, xb.z, xa.w, xb.w)
        xa = na; xb = nb; na = xrA[2]; nb = xrB[2];
        ACCP(w0x_L, 2, xa.x, xb.x, xa.y, xb.y)
        ACCP(w0x_L, 3, xa.z, xb.z, xa.w, xb.w)
        xa = na; xb = nb; na = xrA[3]; nb = xrB[3];
        ACCP(w0x_L, 4, xa.x, xb.x, xa.y, xb.y)
        ACCP(w0x_L, 5, xa.z, xb.z, xa.w, xb.w)
        xa = na; xb = nb; na = xrA[4]; nb = xrB[4];
        ACCP(w0x_L, 6, xa.x, xb.x, xa.y, xb.y)
        ACCP(w0x_L, 7, xa.z, xb.z, xa.w, xb.w)
        xa = na; xb = nb; na = xrA[5]; nb = xrB[5];
        ACCP(w0x_L, 8, xa.x, xb.x, xa.y, xb.y)
        ACCP(w0x_L, 9, xa.z, xb.z, xa.w, xb.w)
        xa = na; xb = nb; na = xrA[6]; nb = xrB[6];
        ACCP(w0x_L, 10, xa.x, xb.x, xa.y, xb.y)
        ACCP(w0x_L, 11, xa.z, xb.z, xa.w, xb.w)
        xa = na; xb = nb;
        ACCP(w0x_L, 12, xa.x, xb.x, xa.y, xb.y)
        ACCP(w0x_L, 13, xa.z, xb.z, xa.w, xb.w)

        // recurrent part of layer 0
        ACCP(w0h_L, 0, h0A[0], h0B[0], h0A[1], h0B[1])
        ACCP(w0h_L, 1, h0A[2], h0B[2], h0A[3], h0B[3])
        ACCP(w0h_L, 2, h0A[4], h0B[4], h0A[5], h0B[5])
        ACCP(w0h_L, 3, h0A[6], h0B[6], h0A[7], h0B[7])
        ACCP(w0h_L, 4, h0A[8], h0B[8], h0A[9], h0B[9])
        EXCH_UPDATE(h0A, h0B, c0m)

        // ---- layer 1 ----
        INIT_BIAS(b1_L)
        ACCP(w1x_L, 0, h0A[0], h0B[0], h0A[1], h0B[1])
        ACCP(w1x_L, 1, h0A[2], h0B[2], h0A[3], h0B[3])
        ACCP(w1x_L, 2, h0A[4], h0B[4], h0A[5], h0B[5])
        ACCP(w1x_L, 3, h0A[6], h0B[6], h0A[7], h0B[7])
        ACCP(w1x_L, 4, h0A[8], h0B[8], h0A[9], h0B[9])
        ACCP(w1h_L, 0, h1A[0], h1B[0], h1A[1], h1B[1])
        ACCP(w1h_L, 1, h1A[2], h1B[2], h1A[3], h1B[3])
        ACCP(w1h_L, 2, h1A[4], h1B[4], h1A[5], h1B[5])
        ACCP(w1h_L, 3, h1A[6], h1B[6], h1A[7], h1B[7])
        ACCP(w1h_L, 4, h1A[8], h1B[8], h1A[9], h1B[9])
        EXCH_UPDATE(h1A, h1B, c1m)
    }

    // classifier head: role0 writes elem A, role2 writes elem B (gmem-direct)
    if ((role & 1) == 0) {
        const int bm = hr ? bB : bA;
        const float *hv = hr ? h1B : h1A;
#pragma unroll
        for (int k = 0; k < 10; k++) {
            float s = __ldg(bcls + k);
#pragma unroll
            for (int j = 0; j < HH; j++) s += hv[j] * __ldg(wcls + k * HH + j);
            out[(size_t)bm * 10 + k] = s;
        }
    }
}

extern "C" void kernel_launch(void *const *d_in, const int *in_sizes, int n_in,
                              void *d_out, int out_size) {
    const float *x    = (const float *)d_in[0];
    const float *wih0 = (const float *)d_in[1];
    const float *whh0 = (const float *)d_in[2];
    const float *bih0 = (const float *)d_in[3];
    const float *bhh0 = (const float *)d_in[4];
    const float *wih1 = (const float *)d_in[5];
    const float *whh1 = (const float *)d_in[6];
    const float *bih1 = (const float *)d_in[7];
    const float *bhh1 = (const float *)d_in[8];
    const float *wcls = (const float *)d_in[9];
    const float *bcls = (const float *)d_in[10];
    float *out = (float *)d_out;

    const int B = in_sizes[0] / (TT * DD);
    const int Bh = B >> 1;
    const int grid = (Bh + 7) / 8;   // 8 quads (16 elems) per 32-thread CTA
    mnist_rnn_kernel<<<grid, 32>>>(x, wih0, whh0, bih0, bhh0,
                                   wih1, whh1, bih1, bhh1,
                                   wcls, bcls, out, B);
}